// round 1
// baseline (speedup 1.0000x reference)
#include <cuda_runtime.h>
#include <math.h>

#define Bsz   4
#define HH    64
#define WW    64
#define C     768
#define HEADS 12
#define HDIM  64
#define NTOK  (Bsz*HH*WW)        // 16384
#define C7    (7*C)              // 5376
#define FFDIM (4*C)              // 3072

// ---------------- scratch (static device globals; no allocs allowed) --------
__device__ float g_xn  [(size_t)NTOK * C];
__device__ float g_proj[(size_t)NTOK * C7];
__device__ float g_O   [(size_t)NTOK * C];
__device__ float g_acc [(size_t)NTOK * C];

// ---------------- block reduction helper ------------------------------------
__device__ __forceinline__ float block_sum256(float v) {
    __shared__ float sh[8];
    int lane = threadIdx.x & 31, w = threadIdx.x >> 5;
    #pragma unroll
    for (int o = 16; o; o >>= 1) v += __shfl_xor_sync(0xFFFFFFFFu, v, o);
    if (lane == 0) sh[w] = v;
    __syncthreads();
    float r = (lane < 8) ? sh[lane] : 0.f;
    if (w == 0) {
        #pragma unroll
        for (int o = 4; o; o >>= 1) r += __shfl_xor_sync(0xFFFFFFFFu, r, o);
        if (lane == 0) sh[0] = r;
    }
    __syncthreads();
    float out = sh[0];
    __syncthreads();
    return out;
}

// ---------------- 1. LayerNorm over C=768 (one block per token) -------------
__global__ void ln_kernel(const float* __restrict__ x,
                          const float* __restrict__ w) {
    int t = blockIdx.x;
    const float* xr = x + (size_t)t * C;
    float v[3];
    float s = 0.f;
    #pragma unroll
    for (int i = 0; i < 3; i++) { v[i] = xr[threadIdx.x + i * 256]; s += v[i]; }
    s = block_sum256(s);
    float mu = s * (1.f / C);
    float vs = 0.f;
    #pragma unroll
    for (int i = 0; i < 3; i++) { float d = v[i] - mu; vs += d * d; }
    vs = block_sum256(vs);
    float inv = rsqrtf(vs * (1.f / C) + 1e-5f);
    #pragma unroll
    for (int i = 0; i < 3; i++) {
        int c = threadIdx.x + i * 256;
        g_xn[(size_t)t * C + c] = (v[i] - mu) * inv * w[c];
    }
}

// ---------------- 2. SGEMM: C[MxN] = A[MxK] * B[KxN] (+bias) (+=) -----------
#define BM 128
#define BN 128
#define BK 8
__global__ void sgemm(const float* __restrict__ A, int lda,
                      const float* __restrict__ B, int ldb,
                      float* __restrict__ Cm, int ldc,
                      int K, const float* __restrict__ bias, int accumulate) {
    __shared__ float As[BK][BM];
    __shared__ float Bsh[BK][BN];
    int tid = threadIdx.x;
    int bm = blockIdx.y * BM;
    int bn = blockIdx.x * BN;
    int a_r = tid >> 1, a_c = (tid & 1) * 4;
    int b_r = tid >> 5, b_c = (tid & 31) * 4;
    int ty = tid >> 4, tx = tid & 15;
    float acc[8][8];
    #pragma unroll
    for (int i = 0; i < 8; i++)
        #pragma unroll
        for (int j = 0; j < 8; j++) acc[i][j] = 0.f;

    for (int k0 = 0; k0 < K; k0 += BK) {
        float4 av = *(const float4*)(A + (size_t)(bm + a_r) * lda + k0 + a_c);
        As[a_c + 0][a_r] = av.x;
        As[a_c + 1][a_r] = av.y;
        As[a_c + 2][a_r] = av.z;
        As[a_c + 3][a_r] = av.w;
        *(float4*)(&Bsh[b_r][b_c]) =
            *(const float4*)(B + (size_t)(k0 + b_r) * ldb + bn + b_c);
        __syncthreads();
        #pragma unroll
        for (int kk = 0; kk < BK; kk++) {
            float a[8], b[8];
            *(float4*)(a)     = *(float4*)(&As[kk][ty * 8]);
            *(float4*)(a + 4) = *(float4*)(&As[kk][ty * 8 + 4]);
            *(float4*)(b)     = *(float4*)(&Bsh[kk][tx * 8]);
            *(float4*)(b + 4) = *(float4*)(&Bsh[kk][tx * 8 + 4]);
            #pragma unroll
            for (int i = 0; i < 8; i++)
                #pragma unroll
                for (int j = 0; j < 8; j++) acc[i][j] += a[i] * b[j];
        }
        __syncthreads();
    }
    #pragma unroll
    for (int i = 0; i < 8; i++) {
        int row = bm + ty * 8 + i;
        #pragma unroll
        for (int j = 0; j < 8; j += 4) {
            int col = bn + tx * 8 + j;
            float4 v = make_float4(acc[i][j], acc[i][j+1], acc[i][j+2], acc[i][j+3]);
            if (bias) {
                v.x += bias[col]; v.y += bias[col+1];
                v.z += bias[col+2]; v.w += bias[col+3];
            }
            float* cp = Cm + (size_t)row * ldc + col;
            if (accumulate) {
                float4 o = *(float4*)cp;
                v.x += o.x; v.y += o.y; v.z += o.z; v.w += o.w;
            }
            *(float4*)cp = v;
        }
    }
}

// ---------------- 3. per-head LN on q and k (one warp per (token,head)) -----
__global__ void qkln_kernel(const float* __restrict__ qw,
                            const float* __restrict__ kw) {
    int gw   = (blockIdx.x * blockDim.x + threadIdx.x) >> 5;   // < NTOK*HEADS
    int lane = threadIdx.x & 31;
    int head = gw % HEADS;
    int t    = gw / HEADS;
    float* base = g_proj + (size_t)t * C7 + head * HDIM;
    #pragma unroll
    for (int which = 0; which < 2; which++) {
        float* v = base + which * C;
        const float* w = which ? kw : qw;
        float x0 = v[lane], x1 = v[lane + 32];
        float s = x0 + x1;
        #pragma unroll
        for (int o = 16; o; o >>= 1) s += __shfl_xor_sync(0xFFFFFFFFu, s, o);
        float mu = s * (1.f / HDIM);
        float d0 = x0 - mu, d1 = x1 - mu;
        float vs = d0 * d0 + d1 * d1;
        #pragma unroll
        for (int o = 16; o; o >>= 1) vs += __shfl_xor_sync(0xFFFFFFFFu, vs, o);
        float inv = rsqrtf(vs * (1.f / HDIM) + 1e-5f);
        v[lane]      = d0 * inv * w[lane];
        v[lane + 32] = d1 * inv * w[lane + 32];
    }
}

// ---------------- 4. axial attention (one block per (b,line,head)) ----------
// AXIS=0: line=h, attend over w.  AXIS=1: line=w, attend over h.
// Output: O[((b*64+query)*64+line)*C + head*64 + c]   (=, then +=)
template <int AXIS>
__global__ void attn_kernel(float* __restrict__ O) {
    extern __shared__ float smem[];
    float* Qs = smem;              // 64x64
    float* Ks = smem + 4096;       // 64x64
    float* Vs = smem + 8192;       // 64x64
    int head = blockIdx.x % HEADS;
    int line = (blockIdx.x / HEADS) % 64;
    int b    = blockIdx.x / (HEADS * 64);
    int tid  = threadIdx.x;

    for (int l = tid; l < 4096; l += 256) {
        int pos = l >> 6, c = l & 63;
        int t = (AXIS == 0) ? ((b * 64 + line) * 64 + pos)
                            : ((b * 64 + pos) * 64 + line);
        const float* base = g_proj + (size_t)t * C7 + head * HDIM + c;
        Qs[l] = base[0];
        Ks[l] = base[C];
        Vs[l] = base[2 * C];
    }
    __syncthreads();

    int row = tid >> 2;            // query position 0..63
    int cq  = (tid & 3) * 16;      // this thread's 16-column strip
    float s[16];
    #pragma unroll
    for (int j = 0; j < 16; j++) s[j] = 0.f;
    for (int c0 = 0; c0 < 64; c0 += 16) {
        float q[16];
        #pragma unroll
        for (int cc = 0; cc < 16; cc++) q[cc] = Qs[row * 64 + c0 + cc];
        #pragma unroll
        for (int j = 0; j < 16; j++)
            #pragma unroll
            for (int cc = 0; cc < 16; cc++)
                s[j] += q[cc] * Ks[(cq + j) * 64 + c0 + cc];
    }
    float m = -1e30f;
    #pragma unroll
    for (int j = 0; j < 16; j++) { s[j] *= 0.125f; m = fmaxf(m, s[j]); }
    m = fmaxf(m, __shfl_xor_sync(0xFFFFFFFFu, m, 1));
    m = fmaxf(m, __shfl_xor_sync(0xFFFFFFFFu, m, 2));
    float sum = 0.f;
    #pragma unroll
    for (int j = 0; j < 16; j++) { s[j] = expf(s[j] - m); sum += s[j]; }
    sum += __shfl_xor_sync(0xFFFFFFFFu, sum, 1);
    sum += __shfl_xor_sync(0xFFFFFFFFu, sum, 2);
    float inv = 1.f / sum;

    __syncthreads();               // done reading Qs
    #pragma unroll
    for (int j = 0; j < 16; j++) Qs[row * 64 + cq + j] = s[j] * inv;  // P
    __syncthreads();

    float o[16];
    #pragma unroll
    for (int cc = 0; cc < 16; cc++) o[cc] = 0.f;
    for (int j = 0; j < 64; j++) {
        float p = Qs[row * 64 + j];
        #pragma unroll
        for (int cc = 0; cc < 16; cc++) o[cc] += p * Vs[j * 64 + cq + cc];
    }
    size_t oi = ((size_t)(b * 64 + row) * 64 + line) * C + head * HDIM + cq;
    #pragma unroll
    for (int cc = 0; cc < 16; cc++) {
        if (AXIS == 0) O[oi + cc] = o[cc];
        else           O[oi + cc] += o[cc];
    }
}

// ---------------- 5. exact GELU on ff columns of proj (in place) ------------
__global__ void gelu_kernel() {
    size_t i = (size_t)blockIdx.x * 256 + threadIdx.x;  // < NTOK*FFDIM
    size_t t = i / FFDIM;
    int    c = (int)(i % FFDIM);
    float* p = g_proj + t * C7 + 3 * C + c;
    float v = *p;
    *p = 0.5f * v * (1.f + erff(v * 0.70710678118654752f));
}

// ---------------- 6. residual epilogue: out = x + gamma * acc ---------------
__global__ void epilogue_kernel(const float* __restrict__ x,
                                const float* __restrict__ gamma,
                                float* __restrict__ out) {
    size_t i = (size_t)blockIdx.x * 256 + threadIdx.x;  // < NTOK*C
    int c = (int)(i % C);
    out[i] = x[i] + gamma[c] * g_acc[i];
}

// ---------------- launch ----------------------------------------------------
extern "C" void kernel_launch(void* const* d_in, const int* in_sizes, int n_in,
                              void* d_out, int out_size) {
    const float* x      = (const float*)d_in[0];
    const float* norm_w = (const float*)d_in[1];
    const float* Wqkv   = (const float*)d_in[2];
    const float* bqkv   = (const float*)d_in[3];
    const float* qnw    = (const float*)d_in[4];
    const float* knw    = (const float*)d_in[5];
    const float* Wout   = (const float*)d_in[6];
    const float* bout   = (const float*)d_in[7];
    const float* Wmlp   = (const float*)d_in[8];
    const float* bmlp   = (const float*)d_in[9];
    const float* gamma  = (const float*)d_in[10];
    float* out = (float*)d_out;

    void *p_xn, *p_proj, *p_O, *p_acc;
    cudaGetSymbolAddress(&p_xn,   g_xn);
    cudaGetSymbolAddress(&p_proj, g_proj);
    cudaGetSymbolAddress(&p_O,    g_O);
    cudaGetSymbolAddress(&p_acc,  g_acc);
    float* xn   = (float*)p_xn;
    float* proj = (float*)p_proj;
    float* Obuf = (float*)p_O;
    float* acc  = (float*)p_acc;

    // 1. LayerNorm
    ln_kernel<<<NTOK, 256>>>(x, norm_w);

    // 2. proj = xn @ Wqkv + bqkv    (16384 x 768 @ 768 x 5376)
    sgemm<<<dim3(C7 / BN, NTOK / BM), 256>>>(xn, C, Wqkv, C7, proj, C7,
                                             C, bqkv, 0);

    // 3. per-head LN on q,k
    qkln_kernel<<<(NTOK * HEADS) / 8, 256>>>(qnw, knw);

    // 4. axial attention: rows then columns
    attn_kernel<0><<<Bsz * 64 * HEADS, 256, 49152>>>(Obuf);
    attn_kernel<1><<<Bsz * 64 * HEADS, 256, 49152>>>(Obuf);

    // 5. GELU(ff) in place
    gelu_kernel<<<(NTOK * FFDIM) / 256, 256>>>();

    // 6. acc = O @ Wout + bout ; acc += gelu(ff) @ Wmlp + bmlp
    sgemm<<<dim3(C / BN, NTOK / BM), 256>>>(Obuf, C, Wout, C, acc, C,
                                            C, bout, 0);
    sgemm<<<dim3(C / BN, NTOK / BM), 256>>>(proj + 3 * C, C7, Wmlp, C, acc, C,
                                            FFDIM, bmlp, 1);

    // 7. out = x + gamma * acc
    epilogue_kernel<<<(NTOK * C) / 256, 256>>>(x, gamma, out);
}

// round 3
// speedup vs baseline: 1.7623x; 1.7623x over previous
#include <cuda_runtime.h>
#include <cuda_bf16.h>
#include <math.h>

#define Bsz   4
#define HH    64
#define WW    64
#define C     768
#define HEADS 12
#define HDIM  64
#define NTOK  (Bsz*HH*WW)        // 16384
#define C7    (7*C)              // 5376
#define FFDIM (4*C)              // 3072

// ---------------- scratch (static device globals; no allocs allowed) --------
__device__ float g_proj[(size_t)NTOK * C7];
__device__ float g_O   [(size_t)NTOK * C];
__device__ float g_acc [(size_t)NTOK * C];
__device__ __nv_bfloat16 g_xn_bf [(size_t)NTOK * C];
__device__ __nv_bfloat16 g_ff_bf [(size_t)NTOK * FFDIM];
__device__ __nv_bfloat16 g_O_bf  [(size_t)NTOK * C];
__device__ __nv_bfloat16 g_Wqkv_bf[(size_t)C * C7];
__device__ __nv_bfloat16 g_Wout_bf[(size_t)C * C];
__device__ __nv_bfloat16 g_Wmlp_bf[(size_t)FFDIM * C];

// ---------------- fp32 -> bf16 conversion -----------------------------------
__global__ void f2bf(const float* __restrict__ in, __nv_bfloat16* __restrict__ out, int n) {
    int i = blockIdx.x * 256 + threadIdx.x;
    if (i < n) out[i] = __float2bfloat16(in[i]);
}

// ---------------- block reduction helper ------------------------------------
__device__ __forceinline__ float block_sum256(float v) {
    __shared__ float sh[8];
    int lane = threadIdx.x & 31, w = threadIdx.x >> 5;
    #pragma unroll
    for (int o = 16; o; o >>= 1) v += __shfl_xor_sync(0xFFFFFFFFu, v, o);
    if (lane == 0) sh[w] = v;
    __syncthreads();
    float r = (lane < 8) ? sh[lane] : 0.f;
    if (w == 0) {
        #pragma unroll
        for (int o = 4; o; o >>= 1) r += __shfl_xor_sync(0xFFFFFFFFu, r, o);
        if (lane == 0) sh[0] = r;
    }
    __syncthreads();
    float out = sh[0];
    __syncthreads();
    return out;
}

// ---------------- 1. LayerNorm over C=768, writes bf16 ----------------------
__global__ void ln_kernel(const float* __restrict__ x,
                          const float* __restrict__ w) {
    int t = blockIdx.x;
    const float* xr = x + (size_t)t * C;
    float v[3];
    float s = 0.f;
    #pragma unroll
    for (int i = 0; i < 3; i++) { v[i] = xr[threadIdx.x + i * 256]; s += v[i]; }
    s = block_sum256(s);
    float mu = s * (1.f / C);
    float vs = 0.f;
    #pragma unroll
    for (int i = 0; i < 3; i++) { float d = v[i] - mu; vs += d * d; }
    vs = block_sum256(vs);
    float inv = rsqrtf(vs * (1.f / C) + 1e-5f);
    #pragma unroll
    for (int i = 0; i < 3; i++) {
        int c = threadIdx.x + i * 256;
        g_xn_bf[(size_t)t * C + c] = __float2bfloat16((v[i] - mu) * inv * w[c]);
    }
}

// ---------------- 2. bf16 tensor-core GEMM (no ldmatrix, direct LDS) --------
// C[MxN](fp32) = A[MxK](bf16,row) * B[KxN](bf16,row) (+bias) (+= optional)
// 128x128 tile, k-step 32, 8 warps of 64x32 fragments, double buffered.
// A staged as [m=128][k=40(pad)]; B staged TRANSPOSED as [n=128][k=40(pad)].
#define TST 40   // tile k-stride in bf16 units (32 + 8 pad); 80B rows, 16B-aligned

__global__ void __launch_bounds__(256) hgemm(
        const __nv_bfloat16* __restrict__ A, int lda,
        const __nv_bfloat16* __restrict__ B, int ldb,
        float* __restrict__ Cm, int ldc, int K,
        const float* __restrict__ bias, int accumulate) {
    __shared__ __align__(16) __nv_bfloat16 As[2][128 * TST];
    __shared__ __align__(16) __nv_bfloat16 Bt[2][128 * TST];

    int tid = threadIdx.x;
    int bm = blockIdx.y * 128, bn = blockIdx.x * 128;
    int w = tid >> 5, lane = tid & 31;
    int wm = (w & 1) * 64, wn = (w >> 1) * 32;
    int grp = lane >> 2, tq = lane & 3;

    float acc[4][4][4];
    #pragma unroll
    for (int i = 0; i < 4; i++)
        #pragma unroll
        for (int j = 0; j < 4; j++)
            #pragma unroll
            for (int k = 0; k < 4; k++) acc[i][j][k] = 0.f;

    uint4 ra[2], rb[2];
    // A loader: idx in [0,512): m = idx>>2, kc = (idx&3)*8
    #define LDA_G(i, kt) ra[i] = *(const uint4*)(A + (size_t)(bm + ((tid + (i)*256) >> 2)) * lda + (kt)*32 + ((tid + (i)*256) & 3) * 8)
    #define STA_S(buf, i) *(uint4*)(&As[buf][((tid + (i)*256) >> 2) * TST + ((tid + (i)*256) & 3) * 8]) = ra[i]
    // B loader: idx in [0,512): k = idx>>4, n8 = (idx&15)*8 ; scatter-transpose
    #define LDB_G(i, kt) rb[i] = *(const uint4*)(B + (size_t)((kt)*32 + ((tid + (i)*256) >> 4)) * ldb + bn + ((tid + (i)*256) & 15) * 8)
    #define STB_S(buf, i) do { \
        int _k = (tid + (i)*256) >> 4, _n8 = ((tid + (i)*256) & 15) * 8;     \
        const __nv_bfloat16* _e = (const __nv_bfloat16*)&rb[i];              \
        _Pragma("unroll")                                                    \
        for (int _j = 0; _j < 8; _j++)                                       \
            Bt[buf][(_n8 + _j) * TST + _k] = _e[_j];                         \
    } while (0)

    LDA_G(0, 0); LDA_G(1, 0); LDB_G(0, 0); LDB_G(1, 0);
    STA_S(0, 0); STA_S(0, 1); STB_S(0, 0); STB_S(0, 1);
    __syncthreads();

    int KT = K / 32;
    for (int kt = 0; kt < KT; kt++) {
        int cur = kt & 1, nxt = cur ^ 1;
        if (kt + 1 < KT) { LDA_G(0, kt + 1); LDA_G(1, kt + 1); LDB_G(0, kt + 1); LDB_G(1, kt + 1); }

        #pragma unroll
        for (int ks = 0; ks < 2; ks++) {
            int kk = ks * 16;
            unsigned a[4][4], b[4][2];
            #pragma unroll
            for (int mt = 0; mt < 4; mt++) {
                const __nv_bfloat16* base = &As[cur][(wm + mt * 16 + grp) * TST + kk + tq * 2];
                a[mt][0] = *(const unsigned*)(base);                 // row grp,   k 0..1
                a[mt][1] = *(const unsigned*)(base + 8 * TST);       // row grp+8, k 0..1
                a[mt][2] = *(const unsigned*)(base + 8);             // row grp,   k 8..9
                a[mt][3] = *(const unsigned*)(base + 8 * TST + 8);   // row grp+8, k 8..9
            }
            #pragma unroll
            for (int nt = 0; nt < 4; nt++) {
                const __nv_bfloat16* base = &Bt[cur][(wn + nt * 8 + grp) * TST + kk + tq * 2];
                b[nt][0] = *(const unsigned*)(base);                 // n grp, k 0..1
                b[nt][1] = *(const unsigned*)(base + 8);             // n grp, k 8..9
            }
            #pragma unroll
            for (int mt = 0; mt < 4; mt++)
                #pragma unroll
                for (int nt = 0; nt < 4; nt++) {
                    asm volatile(
                        "mma.sync.aligned.m16n8k16.row.col.f32.bf16.bf16.f32 "
                        "{%0,%1,%2,%3}, {%4,%5,%6,%7}, {%8,%9}, {%0,%1,%2,%3};"
                        : "+f"(acc[mt][nt][0]), "+f"(acc[mt][nt][1]),
                          "+f"(acc[mt][nt][2]), "+f"(acc[mt][nt][3])
                        : "r"(a[mt][0]), "r"(a[mt][1]), "r"(a[mt][2]), "r"(a[mt][3]),
                          "r"(b[nt][0]), "r"(b[nt][1]));
                }
        }

        if (kt + 1 < KT) {
            STA_S(nxt, 0); STA_S(nxt, 1); STB_S(nxt, 0); STB_S(nxt, 1);
            __syncthreads();
        }
    }

    // epilogue: c0,c1 -> (row grp, col tq*2..+1); c2,c3 -> row grp+8
    #pragma unroll
    for (int mt = 0; mt < 4; mt++) {
        #pragma unroll
        for (int nt = 0; nt < 4; nt++) {
            int row = bm + wm + mt * 16 + grp;
            int col = bn + wn + nt * 8 + tq * 2;
            float b0 = bias ? bias[col] : 0.f;
            float b1 = bias ? bias[col + 1] : 0.f;
            float* p0 = Cm + (size_t)row * ldc + col;
            float* p1 = p0 + 8 * ldc;
            float2 v0 = make_float2(acc[mt][nt][0] + b0, acc[mt][nt][1] + b1);
            float2 v1 = make_float2(acc[mt][nt][2] + b0, acc[mt][nt][3] + b1);
            if (accumulate) {
                float2 o0 = *(float2*)p0, o1 = *(float2*)p1;
                v0.x += o0.x; v0.y += o0.y; v1.x += o1.x; v1.y += o1.y;
            }
            *(float2*)p0 = v0;
            *(float2*)p1 = v1;
        }
    }
}

// ---------------- 3. per-head LN on q and k (one warp per (token,head)) -----
__global__ void qkln_kernel(const float* __restrict__ qw,
                            const float* __restrict__ kw) {
    int gw   = (blockIdx.x * blockDim.x + threadIdx.x) >> 5;
    int lane = threadIdx.x & 31;
    int head = gw % HEADS;
    int t    = gw / HEADS;
    float* base = g_proj + (size_t)t * C7 + head * HDIM;
    #pragma unroll
    for (int which = 0; which < 2; which++) {
        float* v = base + which * C;
        const float* w = which ? kw : qw;
        float x0 = v[lane], x1 = v[lane + 32];
        float s = x0 + x1;
        #pragma unroll
        for (int o = 16; o; o >>= 1) s += __shfl_xor_sync(0xFFFFFFFFu, s, o);
        float mu = s * (1.f / HDIM);
        float d0 = x0 - mu, d1 = x1 - mu;
        float vs = d0 * d0 + d1 * d1;
        #pragma unroll
        for (int o = 16; o; o >>= 1) vs += __shfl_xor_sync(0xFFFFFFFFu, vs, o);
        float inv = rsqrtf(vs * (1.f / HDIM) + 1e-5f);
        v[lane]      = d0 * inv * w[lane];
        v[lane + 32] = d1 * inv * w[lane + 32];
    }
}

// ---------------- 4. axial attention (one block per (b,line,head)) ----------
template <int AXIS>
__global__ void attn_kernel(float* __restrict__ O) {
    extern __shared__ float smem[];
    float* Qs = smem;
    float* Ks = smem + 4096;
    float* Vs = smem + 8192;
    int head = blockIdx.x % HEADS;
    int line = (blockIdx.x / HEADS) % 64;
    int b    = blockIdx.x / (HEADS * 64);
    int tid  = threadIdx.x;

    for (int l = tid; l < 4096; l += 256) {
        int pos = l >> 6, c = l & 63;
        int t = (AXIS == 0) ? ((b * 64 + line) * 64 + pos)
                            : ((b * 64 + pos) * 64 + line);
        const float* base = g_proj + (size_t)t * C7 + head * HDIM + c;
        Qs[l] = base[0];
        Ks[l] = base[C];
        Vs[l] = base[2 * C];
    }
    __syncthreads();

    int row = tid >> 2;
    int cq  = (tid & 3) * 16;
    float s[16];
    #pragma unroll
    for (int j = 0; j < 16; j++) s[j] = 0.f;
    for (int c0 = 0; c0 < 64; c0 += 16) {
        float q[16];
        #pragma unroll
        for (int cc = 0; cc < 16; cc++) q[cc] = Qs[row * 64 + c0 + cc];
        #pragma unroll
        for (int j = 0; j < 16; j++)
            #pragma unroll
            for (int cc = 0; cc < 16; cc++)
                s[j] += q[cc] * Ks[(cq + j) * 64 + c0 + cc];
    }
    float m = -1e30f;
    #pragma unroll
    for (int j = 0; j < 16; j++) { s[j] *= 0.125f; m = fmaxf(m, s[j]); }
    m = fmaxf(m, __shfl_xor_sync(0xFFFFFFFFu, m, 1));
    m = fmaxf(m, __shfl_xor_sync(0xFFFFFFFFu, m, 2));
    float sum = 0.f;
    #pragma unroll
    for (int j = 0; j < 16; j++) { s[j] = expf(s[j] - m); sum += s[j]; }
    sum += __shfl_xor_sync(0xFFFFFFFFu, sum, 1);
    sum += __shfl_xor_sync(0xFFFFFFFFu, sum, 2);
    float inv = 1.f / sum;

    __syncthreads();
    #pragma unroll
    for (int j = 0; j < 16; j++) Qs[row * 64 + cq + j] = s[j] * inv;
    __syncthreads();

    float o[16];
    #pragma unroll
    for (int cc = 0; cc < 16; cc++) o[cc] = 0.f;
    for (int j = 0; j < 64; j++) {
        float p = Qs[row * 64 + j];
        #pragma unroll
        for (int cc = 0; cc < 16; cc++) o[cc] += p * Vs[j * 64 + cq + cc];
    }
    size_t oi = ((size_t)(b * 64 + row) * 64 + line) * C + head * HDIM + cq;
    #pragma unroll
    for (int cc = 0; cc < 16; cc++) {
        if (AXIS == 0) O[oi + cc] = o[cc];
        else           g_O_bf[oi + cc] = __float2bfloat16(O[oi + cc] + o[cc]);
    }
}

// ---------------- 5. exact GELU on ff columns of proj -> bf16 ---------------
__global__ void gelu_kernel() {
    size_t i = (size_t)blockIdx.x * 256 + threadIdx.x;
    size_t t = i / FFDIM;
    int    c = (int)(i % FFDIM);
    float v = g_proj[t * C7 + 3 * C + c];
    g_ff_bf[i] = __float2bfloat16(0.5f * v * (1.f + erff(v * 0.70710678118654752f)));
}

// ---------------- 6. residual epilogue: out = x + gamma * acc ---------------
__global__ void epilogue_kernel(const float* __restrict__ x,
                                const float* __restrict__ gamma,
                                float* __restrict__ out) {
    size_t i = (size_t)blockIdx.x * 256 + threadIdx.x;
    int c = (int)(i % C);
    out[i] = x[i] + gamma[c] * g_acc[i];
}

// ---------------- launch ----------------------------------------------------
extern "C" void kernel_launch(void* const* d_in, const int* in_sizes, int n_in,
                              void* d_out, int out_size) {
    const float* x      = (const float*)d_in[0];
    const float* norm_w = (const float*)d_in[1];
    const float* Wqkv   = (const float*)d_in[2];
    const float* bqkv   = (const float*)d_in[3];
    const float* qnw    = (const float*)d_in[4];
    const float* knw    = (const float*)d_in[5];
    const float* Wout   = (const float*)d_in[6];
    const float* bout   = (const float*)d_in[7];
    const float* Wmlp   = (const float*)d_in[8];
    const float* bmlp   = (const float*)d_in[9];
    const float* gamma  = (const float*)d_in[10];
    float* out = (float*)d_out;

    void *p_proj, *p_O, *p_acc, *p_xnb, *p_ffb, *p_Ob, *p_wq, *p_wo, *p_wm;
    cudaGetSymbolAddress(&p_proj, g_proj);
    cudaGetSymbolAddress(&p_O,    g_O);
    cudaGetSymbolAddress(&p_acc,  g_acc);
    cudaGetSymbolAddress(&p_xnb,  g_xn_bf);
    cudaGetSymbolAddress(&p_ffb,  g_ff_bf);
    cudaGetSymbolAddress(&p_Ob,   g_O_bf);
    cudaGetSymbolAddress(&p_wq,   g_Wqkv_bf);
    cudaGetSymbolAddress(&p_wo,   g_Wout_bf);
    cudaGetSymbolAddress(&p_wm,   g_Wmlp_bf);
    float* proj = (float*)p_proj;
    float* Obuf = (float*)p_O;
    float* acc  = (float*)p_acc;

    // 0. convert weights to bf16
    f2bf<<<(C * C7 + 255) / 256, 256>>>(Wqkv, (__nv_bfloat16*)p_wq, C * C7);
    f2bf<<<(C * C + 255) / 256, 256>>>(Wout, (__nv_bfloat16*)p_wo, C * C);
    f2bf<<<(FFDIM * C + 255) / 256, 256>>>(Wmlp, (__nv_bfloat16*)p_wm, FFDIM * C);

    // 1. LayerNorm -> bf16 xn
    ln_kernel<<<NTOK, 256>>>(x, norm_w);

    // 2. proj = xn @ Wqkv + bqkv   (16384 x 5376, K=768)
    hgemm<<<dim3(C7 / 128, NTOK / 128), 256>>>(
        (const __nv_bfloat16*)p_xnb, C, (const __nv_bfloat16*)p_wq, C7,
        proj, C7, C, bqkv, 0);

    // 3. per-head LN on q,k
    qkln_kernel<<<(NTOK * HEADS) / 8, 256>>>(qnw, knw);

    // 4. axial attention (axis1 writes bf16 O)
    attn_kernel<0><<<Bsz * 64 * HEADS, 256, 49152>>>(Obuf);
    attn_kernel<1><<<Bsz * 64 * HEADS, 256, 49152>>>(Obuf);

    // 5. GELU(ff) -> bf16
    gelu_kernel<<<(NTOK * FFDIM) / 256, 256>>>();

    // 6. acc = O @ Wout + bout ; acc += gelu(ff) @ Wmlp + bmlp
    hgemm<<<dim3(C / 128, NTOK / 128), 256>>>(
        (const __nv_bfloat16*)p_Ob, C, (const __nv_bfloat16*)p_wo, C,
        acc, C, C, bout, 0);
    hgemm<<<dim3(C / 128, NTOK / 128), 256>>>(
        (const __nv_bfloat16*)p_ffb, FFDIM, (const __nv_bfloat16*)p_wm, C,
        acc, C, FFDIM, bmlp, 1);

    // 7. out = x + gamma * acc
    epilogue_kernel<<<(NTOK * C) / 256, 256>>>(x, gamma, out);
}

// round 4
// speedup vs baseline: 5.2140x; 2.9586x over previous
#include <cuda_runtime.h>
#include <cuda_bf16.h>
#include <math.h>

#define Bsz   4
#define C     768
#define HEADS 12
#define HDIM  64
#define NTOK  (Bsz*64*64)        // 16384
#define C7    (7*C)              // 5376
#define FFDIM (4*C)              // 3072
#define QKV   (3*C)              // 2304
#define CAT   (C + FFDIM)        // 3840

// ---------------- scratch (static device globals) ---------------------------
__device__ float g_proj[(size_t)NTOK * QKV];            // q|k|v fp32
__device__ float g_O   [(size_t)NTOK * C];              // axis-0 attention out
__device__ __nv_bfloat16 g_xn_bf [(size_t)NTOK * C];    // LN(x) bf16
__device__ __nv_bfloat16 g_cat   [(size_t)NTOK * CAT];  // [attnO | gelu(ff)] bf16
__device__ __nv_bfloat16 g_Wqkv_t[(size_t)C7 * C];      // Wqkv^T bf16  [n][k]
__device__ __nv_bfloat16 g_Wcat_t[(size_t)C * CAT];     // [Wout;Wmlp]^T bf16 [n][k]

// ---------------- weight transpose+convert: out[n][k] = in[k][n] ------------
__global__ void transpose_w(const float* __restrict__ in, __nv_bfloat16* __restrict__ out,
                            int N, int ldout, int koff) {
    __shared__ float tile[32][33];
    int n0 = blockIdx.x * 32, k0 = blockIdx.y * 32;
    int tx = threadIdx.x, ty = threadIdx.y;
    #pragma unroll
    for (int r = 0; r < 32; r += 8)
        tile[ty + r][tx] = in[(size_t)(k0 + ty + r) * N + n0 + tx];
    __syncthreads();
    #pragma unroll
    for (int r = 0; r < 32; r += 8)
        out[(size_t)(n0 + ty + r) * ldout + koff + k0 + tx] =
            __float2bfloat16(tile[tx][ty + r]);
}

// ---------------- block reduction helper ------------------------------------
__device__ __forceinline__ float block_sum256(float v) {
    __shared__ float sh[8];
    int lane = threadIdx.x & 31, w = threadIdx.x >> 5;
    #pragma unroll
    for (int o = 16; o; o >>= 1) v += __shfl_xor_sync(0xFFFFFFFFu, v, o);
    if (lane == 0) sh[w] = v;
    __syncthreads();
    float r = (lane < 8) ? sh[lane] : 0.f;
    if (w == 0) {
        #pragma unroll
        for (int o = 4; o; o >>= 1) r += __shfl_xor_sync(0xFFFFFFFFu, r, o);
        if (lane == 0) sh[0] = r;
    }
    __syncthreads();
    float out = sh[0];
    __syncthreads();
    return out;
}

// ---------------- 1. LayerNorm over C=768, writes bf16 ----------------------
__global__ void ln_kernel(const float* __restrict__ x,
                          const float* __restrict__ w) {
    int t = blockIdx.x;
    const float* xr = x + (size_t)t * C;
    float v[3];
    float s = 0.f;
    #pragma unroll
    for (int i = 0; i < 3; i++) { v[i] = xr[threadIdx.x + i * 256]; s += v[i]; }
    s = block_sum256(s);
    float mu = s * (1.f / C);
    float vs = 0.f;
    #pragma unroll
    for (int i = 0; i < 3; i++) { float d = v[i] - mu; vs += d * d; }
    vs = block_sum256(vs);
    float inv = rsqrtf(vs * (1.f / C) + 1e-5f);
    #pragma unroll
    for (int i = 0; i < 3; i++) {
        int c = threadIdx.x + i * 256;
        g_xn_bf[(size_t)t * C + c] = __float2bfloat16((v[i] - mu) * inv * w[c]);
    }
}

// ---------------- 2. bf16 tensor-core GEMM, both operands [row][k] ----------
#define TST 40

__device__ __forceinline__ float gelu_exact(float v) {
    return 0.5f * v * (1.f + erff(v * 0.70710678118654752f));
}

__global__ void __launch_bounds__(256) hgemm(
        const __nv_bfloat16* __restrict__ A, int lda,
        const __nv_bfloat16* __restrict__ Bt, int ldb, int K,
        const float* __restrict__ bias1, const float* __restrict__ bias2,
        const float* __restrict__ xres, const float* __restrict__ gamma,
        float* __restrict__ outp, int mode) {
    __shared__ __align__(16) __nv_bfloat16 As[2][128 * TST];
    __shared__ __align__(16) __nv_bfloat16 Bs[2][128 * TST];

    int tid = threadIdx.x;
    int bm = blockIdx.y * 128, bn = blockIdx.x * 128;
    int w = tid >> 5, lane = tid & 31;
    int wm = (w & 1) * 64, wn = (w >> 1) * 32;
    int grp = lane >> 2, tq = lane & 3;

    float acc[4][4][4];
    #pragma unroll
    for (int i = 0; i < 4; i++)
        #pragma unroll
        for (int j = 0; j < 4; j++)
            #pragma unroll
            for (int k = 0; k < 4; k++) acc[i][j][k] = 0.f;

    uint4 ra[2], rb[2];
    #define LDG_T(reg, P, base, ld, i, kt) \
        reg[i] = *(const uint4*)(P + (size_t)(base + ((tid + (i)*256) >> 2)) * ld + (kt)*32 + ((tid + (i)*256) & 3) * 8)
    #define STS_T(dst, reg, buf, i) \
        *(uint4*)(&dst[buf][((tid + (i)*256) >> 2) * TST + ((tid + (i)*256) & 3) * 8]) = reg[i]

    LDG_T(ra, A, bm, lda, 0, 0); LDG_T(ra, A, bm, lda, 1, 0);
    LDG_T(rb, Bt, bn, ldb, 0, 0); LDG_T(rb, Bt, bn, ldb, 1, 0);
    STS_T(As, ra, 0, 0); STS_T(As, ra, 0, 1);
    STS_T(Bs, rb, 0, 0); STS_T(Bs, rb, 0, 1);
    __syncthreads();

    int KT = K / 32;
    for (int kt = 0; kt < KT; kt++) {
        int cur = kt & 1, nxt = cur ^ 1;
        if (kt + 1 < KT) {
            LDG_T(ra, A, bm, lda, 0, kt + 1); LDG_T(ra, A, bm, lda, 1, kt + 1);
            LDG_T(rb, Bt, bn, ldb, 0, kt + 1); LDG_T(rb, Bt, bn, ldb, 1, kt + 1);
        }

        #pragma unroll
        for (int ks = 0; ks < 2; ks++) {
            int kk = ks * 16;
            unsigned a[4][4], b[4][2];
            #pragma unroll
            for (int mt = 0; mt < 4; mt++) {
                const __nv_bfloat16* base = &As[cur][(wm + mt * 16 + grp) * TST + kk + tq * 2];
                a[mt][0] = *(const unsigned*)(base);
                a[mt][1] = *(const unsigned*)(base + 8 * TST);
                a[mt][2] = *(const unsigned*)(base + 8);
                a[mt][3] = *(const unsigned*)(base + 8 * TST + 8);
            }
            #pragma unroll
            for (int nt = 0; nt < 4; nt++) {
                const __nv_bfloat16* base = &Bs[cur][(wn + nt * 8 + grp) * TST + kk + tq * 2];
                b[nt][0] = *(const unsigned*)(base);
                b[nt][1] = *(const unsigned*)(base + 8);
            }
            #pragma unroll
            for (int mt = 0; mt < 4; mt++)
                #pragma unroll
                for (int nt = 0; nt < 4; nt++) {
                    asm volatile(
                        "mma.sync.aligned.m16n8k16.row.col.f32.bf16.bf16.f32 "
                        "{%0,%1,%2,%3}, {%4,%5,%6,%7}, {%8,%9}, {%0,%1,%2,%3};"
                        : "+f"(acc[mt][nt][0]), "+f"(acc[mt][nt][1]),
                          "+f"(acc[mt][nt][2]), "+f"(acc[mt][nt][3])
                        : "r"(a[mt][0]), "r"(a[mt][1]), "r"(a[mt][2]), "r"(a[mt][3]),
                          "r"(b[nt][0]), "r"(b[nt][1]));
                }
        }

        if (kt + 1 < KT) {
            STS_T(As, ra, nxt, 0); STS_T(As, ra, nxt, 1);
            STS_T(Bs, rb, nxt, 0); STS_T(Bs, rb, nxt, 1);
            __syncthreads();
        }
    }

    #pragma unroll
    for (int mt = 0; mt < 4; mt++) {
        #pragma unroll
        for (int nt = 0; nt < 4; nt++) {
            int row0 = bm + wm + mt * 16 + grp;
            int col  = bn + wn + nt * 8 + tq * 2;
            #pragma unroll
            for (int half = 0; half < 2; half++) {
                int row = row0 + half * 8;
                float v0 = acc[mt][nt][half * 2 + 0];
                float v1 = acc[mt][nt][half * 2 + 1];
                if (mode == 0) {
                    v0 += bias1[col]; v1 += bias1[col + 1];
                    if (col < QKV) {
                        float* p = g_proj + (size_t)row * QKV + col;
                        p[0] = v0; p[1] = v1;
                    } else {
                        __nv_bfloat16* p = g_cat + (size_t)row * CAT + col - 1536;
                        p[0] = __float2bfloat16(gelu_exact(v0));
                        p[1] = __float2bfloat16(gelu_exact(v1));
                    }
                } else {
                    size_t p = (size_t)row * C + col;
                    outp[p]     = xres[p]     + gamma[col]     * (v0 + bias1[col]     + bias2[col]);
                    outp[p + 1] = xres[p + 1] + gamma[col + 1] * (v1 + bias1[col + 1] + bias2[col + 1]);
                }
            }
        }
    }
}

// ---------------- 3. axial attention with fused q/k LayerNorm ---------------
template <int AXIS>
__global__ void __launch_bounds__(256) attn_kernel(const float* __restrict__ qw,
                                                   const float* __restrict__ kw) {
    __shared__ float Qs[64 * 64];   // Q (LN'd), later P
    __shared__ float KV[64 * 68];   // K transposed [c][pos], later V [pos][c]
    int head = blockIdx.x % HEADS;
    int line = (blockIdx.x / HEADS) % 64;
    int b    = blockIdx.x / (HEADS * 64);
    int tid  = threadIdx.x;

    #define TOK(pos) (AXIS == 0 ? ((b * 64 + line) * 64 + (pos)) : ((b * 64 + (pos)) * 64 + line))

    // ---- load Q,K with fused per-head LN (4 threads per row) ----
    {
        int row = tid >> 2, seg = tid & 3;
        const float* gq = g_proj + (size_t)TOK(row) * QKV + head * HDIM + seg * 16;
        float q[16], k[16];
        #pragma unroll
        for (int wv = 0; wv < 4; wv++) {
            *(float4*)(q + wv * 4) = *(const float4*)(gq + wv * 4);
            *(float4*)(k + wv * 4) = *(const float4*)(gq + C + wv * 4);
        }
        float sq = 0.f, sk = 0.f, sq2 = 0.f, sk2 = 0.f;
        #pragma unroll
        for (int e = 0; e < 16; e++) { sq += q[e]; sk += k[e]; sq2 += q[e]*q[e]; sk2 += k[e]*k[e]; }
        #pragma unroll
        for (int o = 1; o <= 2; o <<= 1) {
            sq  += __shfl_xor_sync(0xFFFFFFFFu, sq,  o);
            sk  += __shfl_xor_sync(0xFFFFFFFFu, sk,  o);
            sq2 += __shfl_xor_sync(0xFFFFFFFFu, sq2, o);
            sk2 += __shfl_xor_sync(0xFFFFFFFFu, sk2, o);
        }
        float muq = sq * (1.f/64.f), muk = sk * (1.f/64.f);
        float invq = rsqrtf(sq2 * (1.f/64.f) - muq * muq + 1e-5f);
        float invk = rsqrtf(sk2 * (1.f/64.f) - muk * muk + 1e-5f);
        #pragma unroll
        for (int e = 0; e < 16; e++) {
            int c = seg * 16 + e;
            Qs[row * 64 + c] = (q[e] - muq) * invq * __ldg(qw + c);
            KV[c * 68 + row] = (k[e] - muk) * invk * __ldg(kw + c);
        }
    }
    __syncthreads();

    int ti = tid >> 4, tj = tid & 15;

    // ---- S = Q K^T (4x4 per thread) ----
    float s[4][4];
    #pragma unroll
    for (int i = 0; i < 4; i++)
        #pragma unroll
        for (int j = 0; j < 4; j++) s[i][j] = 0.f;
    #pragma unroll 4
    for (int c = 0; c < 64; c++) {
        float4 k4 = *(const float4*)&KV[c * 68 + tj * 4];
        float q0 = Qs[(ti * 4 + 0) * 64 + c];
        float q1 = Qs[(ti * 4 + 1) * 64 + c];
        float q2 = Qs[(ti * 4 + 2) * 64 + c];
        float q3 = Qs[(ti * 4 + 3) * 64 + c];
        s[0][0] += q0*k4.x; s[0][1] += q0*k4.y; s[0][2] += q0*k4.z; s[0][3] += q0*k4.w;
        s[1][0] += q1*k4.x; s[1][1] += q1*k4.y; s[1][2] += q1*k4.z; s[1][3] += q1*k4.w;
        s[2][0] += q2*k4.x; s[2][1] += q2*k4.y; s[2][2] += q2*k4.z; s[2][3] += q2*k4.w;
        s[3][0] += q3*k4.x; s[3][1] += q3*k4.y; s[3][2] += q3*k4.z; s[3][3] += q3*k4.w;
    }

    // ---- softmax per row ----
    #pragma unroll
    for (int i = 0; i < 4; i++) {
        float m = -1e30f;
        #pragma unroll
        for (int j = 0; j < 4; j++) { s[i][j] *= 0.125f; m = fmaxf(m, s[i][j]); }
        #pragma unroll
        for (int o = 8; o; o >>= 1) m = fmaxf(m, __shfl_xor_sync(0xFFFFFFFFu, m, o));
        float r = 0.f;
        #pragma unroll
        for (int j = 0; j < 4; j++) { s[i][j] = __expf(s[i][j] - m); r += s[i][j]; }
        #pragma unroll
        for (int o = 8; o; o >>= 1) r += __shfl_xor_sync(0xFFFFFFFFu, r, o);
        float inv = 1.f / r;
        #pragma unroll
        for (int j = 0; j < 4; j++) s[i][j] *= inv;
    }

    __syncthreads();

    // ---- write P into Qs; load V into KV ----
    #pragma unroll
    for (int i = 0; i < 4; i++)
        #pragma unroll
        for (int j = 0; j < 4; j++)
            Qs[(ti * 4 + i) * 64 + tj * 4 + j] = s[i][j];
    #pragma unroll
    for (int it = 0; it < 4; it++) {
        int idx = tid + it * 256;
        int pos = idx >> 4, c4 = (idx & 15) * 4;
        *(float4*)&KV[pos * 68 + c4] =
            *(const float4*)(g_proj + (size_t)TOK(pos) * QKV + 2 * C + head * HDIM + c4);
    }
    __syncthreads();

    // ---- O = P V (4x4 per thread) ----
    float o[4][4];
    #pragma unroll
    for (int i = 0; i < 4; i++)
        #pragma unroll
        for (int j = 0; j < 4; j++) o[i][j] = 0.f;
    #pragma unroll 4
    for (int j = 0; j < 64; j++) {
        float4 v4 = *(const float4*)&KV[j * 68 + tj * 4];
        float p0 = Qs[(ti * 4 + 0) * 64 + j];
        float p1 = Qs[(ti * 4 + 1) * 64 + j];
        float p2 = Qs[(ti * 4 + 2) * 64 + j];
        float p3 = Qs[(ti * 4 + 3) * 64 + j];
        o[0][0] += p0*v4.x; o[0][1] += p0*v4.y; o[0][2] += p0*v4.z; o[0][3] += p0*v4.w;
        o[1][0] += p1*v4.x; o[1][1] += p1*v4.y; o[1][2] += p1*v4.z; o[1][3] += p1*v4.w;
        o[2][0] += p2*v4.x; o[2][1] += p2*v4.y; o[2][2] += p2*v4.z; o[2][3] += p2*v4.w;
        o[3][0] += p3*v4.x; o[3][1] += p3*v4.y; o[3][2] += p3*v4.z; o[3][3] += p3*v4.w;
    }

    int colbase = head * HDIM + tj * 4;
    #pragma unroll
    for (int i = 0; i < 4; i++) {
        int ri = ti * 4 + i;
        size_t tokout = (size_t)((b * 64 + ri) * 64 + line);
        if (AXIS == 0) {
            *(float4*)&g_O[tokout * C + colbase] =
                make_float4(o[i][0], o[i][1], o[i][2], o[i][3]);
        } else {
            float4 prev = *(const float4*)&g_O[tokout * C + colbase];
            __nv_bfloat162 h0 = __floats2bfloat162_rn(prev.x + o[i][0], prev.y + o[i][1]);
            __nv_bfloat162 h1 = __floats2bfloat162_rn(prev.z + o[i][2], prev.w + o[i][3]);
            uint2 u;
            u.x = *(unsigned*)&h0; u.y = *(unsigned*)&h1;
            *(uint2*)&g_cat[tokout * CAT + colbase] = u;
        }
    }
    #undef TOK
}

// ---------------- launch ----------------------------------------------------
extern "C" void kernel_launch(void* const* d_in, const int* in_sizes, int n_in,
                              void* d_out, int out_size) {
    const float* x      = (const float*)d_in[0];
    const float* norm_w = (const float*)d_in[1];
    const float* Wqkv   = (const float*)d_in[2];
    const float* bqkv   = (const float*)d_in[3];
    const float* qnw    = (const float*)d_in[4];
    const float* knw    = (const float*)d_in[5];
    const float* Wout   = (const float*)d_in[6];
    const float* bout   = (const float*)d_in[7];
    const float* Wmlp   = (const float*)d_in[8];
    const float* bmlp   = (const float*)d_in[9];
    const float* gamma  = (const float*)d_in[10];
    float* out = (float*)d_out;

    void *p_xnb, *p_cat, *p_wq, *p_wc;
    cudaGetSymbolAddress(&p_xnb, g_xn_bf);
    cudaGetSymbolAddress(&p_cat, g_cat);
    cudaGetSymbolAddress(&p_wq,  g_Wqkv_t);
    cudaGetSymbolAddress(&p_wc,  g_Wcat_t);

    // 0. transpose+convert weights
    transpose_w<<<dim3(C7 / 32, C / 32), dim3(32, 8)>>>(Wqkv, (__nv_bfloat16*)p_wq, C7, C, 0);
    transpose_w<<<dim3(C / 32, C / 32), dim3(32, 8)>>>(Wout, (__nv_bfloat16*)p_wc, C, CAT, 0);
    transpose_w<<<dim3(C / 32, FFDIM / 32), dim3(32, 8)>>>(Wmlp, (__nv_bfloat16*)p_wc, C, CAT, C);

    // 1. LayerNorm -> bf16 xn
    ln_kernel<<<NTOK, 256>>>(x, norm_w);

    // 2. fused qkv+ff GEMM (q,k,v fp32 -> g_proj; gelu(ff) bf16 -> g_cat)
    hgemm<<<dim3(C7 / 128, NTOK / 128), 256>>>(
        (const __nv_bfloat16*)p_xnb, C, (const __nv_bfloat16*)p_wq, C,
        C, bqkv, nullptr, nullptr, nullptr, nullptr, 0);

    // 3. axial attention (q/k LN fused in-kernel)
    attn_kernel<0><<<Bsz * 64 * HEADS, 256>>>(qnw, knw);
    attn_kernel<1><<<Bsz * 64 * HEADS, 256>>>(qnw, knw);

    // 4. fused output GEMM + residual epilogue
    hgemm<<<dim3(C / 128, NTOK / 128), 256>>>(
        (const __nv_bfloat16*)p_cat, CAT, (const __nv_bfloat16*)p_wc, CAT,
        CAT, bout, bmlp, x, gamma, out, 1);
}

// round 6
// speedup vs baseline: 6.4601x; 1.2390x over previous
#include <cuda_runtime.h>
#include <cuda_bf16.h>
#include <math.h>
#include <stdint.h>

#define Bsz   4
#define C     768
#define HEADS 12
#define HDIM  64
#define NTOK  (Bsz*64*64)        // 16384
#define C7    (7*C)              // 5376
#define FFDIM (4*C)              // 3072
#define QKV   (3*C)              // 2304
#define CAT   (C + FFDIM)        // 3840

// ---------------- scratch (static device globals) ---------------------------
__device__ float g_proj[(size_t)NTOK * QKV];            // q|k|v fp32
__device__ float g_O   [(size_t)NTOK * C];              // axis-0 attention out
__device__ __nv_bfloat16 g_xn_bf [(size_t)NTOK * C];    // LN(x) bf16
__device__ __nv_bfloat16 g_cat   [(size_t)NTOK * CAT];  // [attnO | gelu(ff)] bf16
__device__ __nv_bfloat16 g_Wqkv_t[(size_t)C7 * C];      // Wqkv^T bf16  [n][k]
__device__ __nv_bfloat16 g_Wcat_t[(size_t)C * CAT];     // [Wout;Wmlp]^T bf16 [n][k]

__device__ __forceinline__ uint32_t smem_u32(const void* p) {
    uint32_t a;
    asm("{ .reg .u64 t; cvta.to.shared.u64 t, %1; cvt.u32.u64 %0, t; }"
        : "=r"(a) : "l"(p));
    return a;
}

// ---------------- weight transpose+convert: out[n][k] = in[k][n] ------------
__global__ void transpose_w(const float* __restrict__ in, __nv_bfloat16* __restrict__ out,
                            int N, int ldout, int koff) {
    __shared__ float tile[32][33];
    int n0 = blockIdx.x * 32, k0 = blockIdx.y * 32;
    int tx = threadIdx.x, ty = threadIdx.y;
    #pragma unroll
    for (int r = 0; r < 32; r += 8)
        tile[ty + r][tx] = in[(size_t)(k0 + ty + r) * N + n0 + tx];
    __syncthreads();
    #pragma unroll
    for (int r = 0; r < 32; r += 8)
        out[(size_t)(n0 + ty + r) * ldout + koff + k0 + tx] =
            __float2bfloat16(tile[tx][ty + r]);
}

// ---------------- block reduction helper ------------------------------------
__device__ __forceinline__ float block_sum256(float v) {
    __shared__ float sh[8];
    int lane = threadIdx.x & 31, w = threadIdx.x >> 5;
    #pragma unroll
    for (int o = 16; o; o >>= 1) v += __shfl_xor_sync(0xFFFFFFFFu, v, o);
    if (lane == 0) sh[w] = v;
    __syncthreads();
    float r = (lane < 8) ? sh[lane] : 0.f;
    if (w == 0) {
        #pragma unroll
        for (int o = 4; o; o >>= 1) r += __shfl_xor_sync(0xFFFFFFFFu, r, o);
        if (lane == 0) sh[0] = r;
    }
    __syncthreads();
    float out = sh[0];
    __syncthreads();
    return out;
}

// ---------------- 1. LayerNorm over C=768, writes bf16 ----------------------
__global__ void ln_kernel(const float* __restrict__ x,
                          const float* __restrict__ w) {
    int t = blockIdx.x;
    const float* xr = x + (size_t)t * C;
    float v[3];
    float s = 0.f;
    #pragma unroll
    for (int i = 0; i < 3; i++) { v[i] = xr[threadIdx.x + i * 256]; s += v[i]; }
    s = block_sum256(s);
    float mu = s * (1.f / C);
    float vs = 0.f;
    #pragma unroll
    for (int i = 0; i < 3; i++) { float d = v[i] - mu; vs += d * d; }
    vs = block_sum256(vs);
    float inv = rsqrtf(vs * (1.f / C) + 1e-5f);
    #pragma unroll
    for (int i = 0; i < 3; i++) {
        int c = threadIdx.x + i * 256;
        g_xn_bf[(size_t)t * C + c] = __float2bfloat16((v[i] - mu) * inv * w[c]);
    }
}

// ---------------- 2. bf16 mma GEMM with cp.async + ldmatrix -----------------
// C[MxN](fp32) = A[MxK] * Bt[NxK]^T. Tiles 128x128, k-step 32, double buffered.
#define TST 40   // k-stride in bf16 (32 + 8 pad); rows 80B, 16B-aligned

__device__ __forceinline__ float gelu_exact(float v) {
    return 0.5f * v * (1.f + erff(v * 0.70710678118654752f));
}

#define MMA16816(d, a, b0v, b1v) \
    asm volatile( \
        "mma.sync.aligned.m16n8k16.row.col.f32.bf16.bf16.f32 " \
        "{%0,%1,%2,%3}, {%4,%5,%6,%7}, {%8,%9}, {%0,%1,%2,%3};" \
        : "+f"((d)[0]), "+f"((d)[1]), "+f"((d)[2]), "+f"((d)[3]) \
        : "r"((a)[0]), "r"((a)[1]), "r"((a)[2]), "r"((a)[3]), \
          "r"(b0v), "r"(b1v))

__global__ void __launch_bounds__(256) hgemm(
        const __nv_bfloat16* __restrict__ A, int lda,
        const __nv_bfloat16* __restrict__ Bt, int ldb, int K,
        const float* __restrict__ bias1, const float* __restrict__ bias2,
        const float* __restrict__ xres, const float* __restrict__ gamma,
        float* __restrict__ outp, int mode) {
    __shared__ __align__(16) __nv_bfloat16 SM[4 * 128 * TST]; // A0,A1,B0,B1
    uint32_t smb = smem_u32(SM);

    int tid = threadIdx.x;
    int bm = blockIdx.y * 128, bn = blockIdx.x * 128;
    int w = tid >> 5, lane = tid & 31;
    int wm = (w & 1) * 64, wn = (w >> 1) * 32;
    int grp = lane >> 2, tq = lane & 3;

    float acc[4][4][4];
    #pragma unroll
    for (int i = 0; i < 4; i++)
        #pragma unroll
        for (int j = 0; j < 4; j++)
            #pragma unroll
            for (int k = 0; k < 4; k++) acc[i][j][k] = 0.f;

    // cp.async staging: idx -> row idx>>2, kchunk (idx&3)*8
    #define CPA(bufbase, P, rowbase, ld, i, kt) do {                              \
        int idx = tid + (i) * 256;                                                \
        uint32_t sa = smb + (uint32_t)((bufbase) + ((idx >> 2) * TST + (idx & 3) * 8)) * 2; \
        const __nv_bfloat16* ga = P + (size_t)((rowbase) + (idx >> 2)) * ld + (kt) * 32 + (idx & 3) * 8; \
        asm volatile("cp.async.cg.shared.global [%0], [%1], 16;" :: "r"(sa), "l"(ga)); \
    } while (0)
    #define CP_COMMIT() asm volatile("cp.async.commit_group;" ::: "memory")
    #define CP_WAIT0()  asm volatile("cp.async.wait_group 0;" ::: "memory")

    const int ABUF0 = 0, ABUF1 = 128 * TST, BBUF0 = 2 * 128 * TST, BBUF1 = 3 * 128 * TST;
    int abuf[2] = { ABUF0, ABUF1 }, bbuf[2] = { BBUF0, BBUF1 };

    CPA(ABUF0, A, bm, lda, 0, 0); CPA(ABUF0, A, bm, lda, 1, 0);
    CPA(BBUF0, Bt, bn, ldb, 0, 0); CPA(BBUF0, Bt, bn, ldb, 1, 0);
    CP_COMMIT();
    CP_WAIT0();
    __syncthreads();

    int KT = K / 32;
    for (int kt = 0; kt < KT; kt++) {
        int cur = kt & 1, nxt = cur ^ 1;
        if (kt + 1 < KT) {
            CPA(abuf[nxt], A, bm, lda, 0, kt + 1); CPA(abuf[nxt], A, bm, lda, 1, kt + 1);
            CPA(bbuf[nxt], Bt, bn, ldb, 0, kt + 1); CPA(bbuf[nxt], Bt, bn, ldb, 1, kt + 1);
            CP_COMMIT();
        }

        #pragma unroll
        for (int ks = 0; ks < 2; ks++) {
            int kk = ks * 16;
            unsigned a[4][4], b[4][2];
            // A fragments: ldmatrix.x4 per m-tile (g=lane>>3: row+=(g&1)*8, col+=(g>>1)*8)
            #pragma unroll
            for (int mt = 0; mt < 4; mt++) {
                int row = wm + mt * 16 + (lane & 7) + ((lane >> 3) & 1) * 8;
                int col = kk + (lane >> 4) * 8;
                uint32_t ad = smb + (uint32_t)(abuf[cur] + row * TST + col) * 2;
                asm volatile("ldmatrix.sync.aligned.m8n8.x4.shared.b16 {%0,%1,%2,%3}, [%4];"
                             : "=r"(a[mt][0]), "=r"(a[mt][1]), "=r"(a[mt][2]), "=r"(a[mt][3])
                             : "r"(ad));
            }
            // B fragments: ldmatrix.x4 per n-tile PAIR (g: nrow+=(g>>1)*8, col+=(g&1)*8)
            #pragma unroll
            for (int p = 0; p < 2; p++) {
                int nrow = wn + p * 16 + (lane & 7) + ((lane >> 4) & 1) * 8;
                int col = kk + ((lane >> 3) & 1) * 8;
                uint32_t bd = smb + (uint32_t)(bbuf[cur] + nrow * TST + col) * 2;
                asm volatile("ldmatrix.sync.aligned.m8n8.x4.shared.b16 {%0,%1,%2,%3}, [%4];"
                             : "=r"(b[2*p][0]), "=r"(b[2*p][1]), "=r"(b[2*p+1][0]), "=r"(b[2*p+1][1])
                             : "r"(bd));
            }
            #pragma unroll
            for (int mt = 0; mt < 4; mt++)
                #pragma unroll
                for (int nt = 0; nt < 4; nt++)
                    MMA16816(acc[mt][nt], a[mt], b[nt][0], b[nt][1]);
        }

        if (kt + 1 < KT) {
            CP_WAIT0();
            __syncthreads();
        }
    }

    #pragma unroll
    for (int mt = 0; mt < 4; mt++) {
        #pragma unroll
        for (int nt = 0; nt < 4; nt++) {
            int row0 = bm + wm + mt * 16 + grp;
            int col  = bn + wn + nt * 8 + tq * 2;
            #pragma unroll
            for (int half = 0; half < 2; half++) {
                int row = row0 + half * 8;
                float v0 = acc[mt][nt][half * 2 + 0];
                float v1 = acc[mt][nt][half * 2 + 1];
                if (mode == 0) {
                    v0 += bias1[col]; v1 += bias1[col + 1];
                    if (col < QKV) {
                        float* p = g_proj + (size_t)row * QKV + col;
                        p[0] = v0; p[1] = v1;
                    } else {
                        __nv_bfloat16* p = g_cat + (size_t)row * CAT + col - 1536;
                        p[0] = __float2bfloat16(gelu_exact(v0));
                        p[1] = __float2bfloat16(gelu_exact(v1));
                    }
                } else {
                    size_t p = (size_t)row * C + col;
                    outp[p]     = xres[p]     + gamma[col]     * (v0 + bias1[col]     + bias2[col]);
                    outp[p + 1] = xres[p + 1] + gamma[col + 1] * (v1 + bias1[col + 1] + bias2[col + 1]);
                }
            }
        }
    }
}

// ---------------- 3. axial attention: mma.sync, fused q/k LN ----------------
// 128 threads = 4 warps; warp w owns query rows w*16 + (grp, grp+8).
#define QST 72   // bf16 row stride (64 + 8 pad)

template <int AXIS>
__global__ void __launch_bounds__(128) attn_kernel(const float* __restrict__ qw,
                                                   const float* __restrict__ kw) {
    __shared__ __align__(16) __nv_bfloat16 Qs[64 * QST];  // [query row][c]
    __shared__ __align__(16) __nv_bfloat16 Ks[64 * QST];  // [key pos][c]
    __shared__ __align__(16) __nv_bfloat16 Vs[64 * QST];  // TRANSPOSED [c][pos]
    int head = blockIdx.x % HEADS;
    int line = (blockIdx.x / HEADS) % 64;
    int b    = blockIdx.x / (HEADS * 64);
    int tid  = threadIdx.x, lane = tid & 31, warp = tid >> 5;

    #define TOK(pos) (AXIS == 0 ? ((b * 64 + line) * 64 + (pos)) : ((b * 64 + (pos)) * 64 + line))

    // ---- Q,K load + per-head LN (2 threads per row, 32 elems each) ----
    {
        int row = tid >> 1, seg = tid & 1;
        const float* gq = g_proj + (size_t)TOK(row) * QKV + head * HDIM + seg * 32;
        float q[32], k[32];
        #pragma unroll
        for (int i = 0; i < 8; i++) {
            *(float4*)(q + i * 4) = *(const float4*)(gq + i * 4);
            *(float4*)(k + i * 4) = *(const float4*)(gq + C + i * 4);
        }
        float sq = 0.f, sk = 0.f, sq2 = 0.f, sk2 = 0.f;
        #pragma unroll
        for (int e = 0; e < 32; e++) { sq += q[e]; sk += k[e]; sq2 += q[e]*q[e]; sk2 += k[e]*k[e]; }
        sq  += __shfl_xor_sync(0xFFFFFFFFu, sq,  1);
        sk  += __shfl_xor_sync(0xFFFFFFFFu, sk,  1);
        sq2 += __shfl_xor_sync(0xFFFFFFFFu, sq2, 1);
        sk2 += __shfl_xor_sync(0xFFFFFFFFu, sk2, 1);
        float muq = sq * (1.f/64.f), muk = sk * (1.f/64.f);
        float invq = rsqrtf(sq2 * (1.f/64.f) - muq * muq + 1e-5f);
        float invk = rsqrtf(sk2 * (1.f/64.f) - muk * muk + 1e-5f);
        #pragma unroll
        for (int e = 0; e < 32; e += 2) {
            int c = seg * 32 + e;
            __nv_bfloat162 hq = __floats2bfloat162_rn((q[e] - muq) * invq * __ldg(qw + c),
                                                      (q[e+1] - muq) * invq * __ldg(qw + c + 1));
            __nv_bfloat162 hk = __floats2bfloat162_rn((k[e] - muk) * invk * __ldg(kw + c),
                                                      (k[e+1] - muk) * invk * __ldg(kw + c + 1));
            *(unsigned*)&Qs[row * QST + c] = *(unsigned*)&hq;
            *(unsigned*)&Ks[row * QST + c] = *(unsigned*)&hk;
        }
    }
    // ---- V load (transposed into Vs[c][pos]) ----
    #pragma unroll
    for (int it = 0; it < 8; it++) {
        int idx = tid + it * 128;
        int pos = idx >> 4, c4 = (idx & 15) * 4;
        float4 v = *(const float4*)(g_proj + (size_t)TOK(pos) * QKV + 2 * C + head * HDIM + c4);
        Vs[(c4 + 0) * QST + pos] = __float2bfloat16(v.x);
        Vs[(c4 + 1) * QST + pos] = __float2bfloat16(v.y);
        Vs[(c4 + 2) * QST + pos] = __float2bfloat16(v.z);
        Vs[(c4 + 3) * QST + pos] = __float2bfloat16(v.w);
    }
    __syncthreads();

    int grp = lane >> 2, tq = lane & 3;
    int row0 = warp * 16;

    // ---- S = Q K^T : fp32 fragments s[nt][4] ----
    float s[8][4];
    #pragma unroll
    for (int nt = 0; nt < 8; nt++)
        #pragma unroll
        for (int j = 0; j < 4; j++) s[nt][j] = 0.f;
    #pragma unroll
    for (int kt = 0; kt < 4; kt++) {
        unsigned a[4];
        const __nv_bfloat16* qb = &Qs[(row0 + grp) * QST + kt * 16 + tq * 2];
        a[0] = *(const unsigned*)(qb);
        a[1] = *(const unsigned*)(qb + 8 * QST);
        a[2] = *(const unsigned*)(qb + 8);
        a[3] = *(const unsigned*)(qb + 8 * QST + 8);
        #pragma unroll
        for (int nt = 0; nt < 8; nt++) {
            const __nv_bfloat16* kb = &Ks[(nt * 8 + grp) * QST + kt * 16 + tq * 2];
            unsigned b0 = *(const unsigned*)(kb);
            unsigned b1 = *(const unsigned*)(kb + 8);
            MMA16816(s[nt], a, b0, b1);
        }
    }

    // ---- softmax: rows row0+grp (regs 0,1) and row0+grp+8 (regs 2,3) ----
    float m0 = -1e30f, m1 = -1e30f;
    #pragma unroll
    for (int nt = 0; nt < 8; nt++) {
        #pragma unroll
        for (int j = 0; j < 4; j++) s[nt][j] *= 0.125f;
        m0 = fmaxf(m0, fmaxf(s[nt][0], s[nt][1]));
        m1 = fmaxf(m1, fmaxf(s[nt][2], s[nt][3]));
    }
    #pragma unroll
    for (int o = 1; o <= 2; o <<= 1) {
        m0 = fmaxf(m0, __shfl_xor_sync(0xFFFFFFFFu, m0, o));
        m1 = fmaxf(m1, __shfl_xor_sync(0xFFFFFFFFu, m1, o));
    }
    float r0 = 0.f, r1 = 0.f;
    #pragma unroll
    for (int nt = 0; nt < 8; nt++) {
        s[nt][0] = __expf(s[nt][0] - m0); s[nt][1] = __expf(s[nt][1] - m0);
        s[nt][2] = __expf(s[nt][2] - m1); s[nt][3] = __expf(s[nt][3] - m1);
        r0 += s[nt][0] + s[nt][1];
        r1 += s[nt][2] + s[nt][3];
    }
    #pragma unroll
    for (int o = 1; o <= 2; o <<= 1) {
        r0 += __shfl_xor_sync(0xFFFFFFFFu, r0, o);
        r1 += __shfl_xor_sync(0xFFFFFFFFu, r1, o);
    }
    float inv0 = 1.f / r0, inv1 = 1.f / r1;

    // ---- pack P to bf16 A-fragments (registers only) ----
    unsigned pf[4][4];
    #pragma unroll
    for (int kt = 0; kt < 4; kt++) {
        __nv_bfloat162 h;
        h = __floats2bfloat162_rn(s[2*kt][0] * inv0, s[2*kt][1] * inv0);   pf[kt][0] = *(unsigned*)&h;
        h = __floats2bfloat162_rn(s[2*kt][2] * inv1, s[2*kt][3] * inv1);   pf[kt][1] = *(unsigned*)&h;
        h = __floats2bfloat162_rn(s[2*kt+1][0] * inv0, s[2*kt+1][1] * inv0); pf[kt][2] = *(unsigned*)&h;
        h = __floats2bfloat162_rn(s[2*kt+1][2] * inv1, s[2*kt+1][3] * inv1); pf[kt][3] = *(unsigned*)&h;
    }

    // ---- O = P V ----
    float o[8][4];
    #pragma unroll
    for (int nt = 0; nt < 8; nt++)
        #pragma unroll
        for (int j = 0; j < 4; j++) o[nt][j] = 0.f;
    #pragma unroll
    for (int kt = 0; kt < 4; kt++) {
        #pragma unroll
        for (int nt = 0; nt < 8; nt++) {
            const __nv_bfloat16* vb = &Vs[(nt * 8 + grp) * QST + kt * 16 + tq * 2];
            unsigned b0 = *(const unsigned*)(vb);
            unsigned b1 = *(const unsigned*)(vb + 8);
            MMA16816(o[nt], pf[kt], b0, b1);
        }
    }

    // ---- write: O[((b*64+qrow)*64+line)*C + head*64 + col] ----
    #pragma unroll
    for (int half = 0; half < 2; half++) {
        int qrow = row0 + grp + half * 8;
        size_t tok = (size_t)((b * 64 + qrow) * 64 + line);
        #pragma unroll
        for (int nt = 0; nt < 8; nt++) {
            int col = head * HDIM + nt * 8 + tq * 2;
            float v0 = o[nt][half * 2 + 0], v1 = o[nt][half * 2 + 1];
            if (AXIS == 0) {
                *(float2*)&g_O[tok * C + col] = make_float2(v0, v1);
            } else {
                float2 prev = *(const float2*)&g_O[tok * C + col];
                __nv_bfloat162 h = __floats2bfloat162_rn(prev.x + v0, prev.y + v1);
                *(unsigned*)&g_cat[tok * CAT + col] = *(unsigned*)&h;
            }
        }
    }
    #undef TOK
}

// ---------------- launch ----------------------------------------------------
extern "C" void kernel_launch(void* const* d_in, const int* in_sizes, int n_in,
                              void* d_out, int out_size) {
    const float* x      = (const float*)d_in[0];
    const float* norm_w = (const float*)d_in[1];
    const float* Wqkv   = (const float*)d_in[2];
    const float* bqkv   = (const float*)d_in[3];
    const float* qnw    = (const float*)d_in[4];
    const float* knw    = (const float*)d_in[5];
    const float* Wout   = (const float*)d_in[6];
    const float* bout   = (const float*)d_in[7];
    const float* Wmlp   = (const float*)d_in[8];
    const float* bmlp   = (const float*)d_in[9];
    const float* gamma  = (const float*)d_in[10];
    float* out = (float*)d_out;

    void *p_xnb, *p_cat, *p_wq, *p_wc;
    cudaGetSymbolAddress(&p_xnb, g_xn_bf);
    cudaGetSymbolAddress(&p_cat, g_cat);
    cudaGetSymbolAddress(&p_wq,  g_Wqkv_t);
    cudaGetSymbolAddress(&p_wc,  g_Wcat_t);

    // 0. transpose+convert weights
    transpose_w<<<dim3(C7 / 32, C / 32), dim3(32, 8)>>>(Wqkv, (__nv_bfloat16*)p_wq, C7, C, 0);
    transpose_w<<<dim3(C / 32, C / 32), dim3(32, 8)>>>(Wout, (__nv_bfloat16*)p_wc, C, CAT, 0);
    transpose_w<<<dim3(C / 32, FFDIM / 32), dim3(32, 8)>>>(Wmlp, (__nv_bfloat16*)p_wc, C, CAT, C);

    // 1. LayerNorm -> bf16 xn
    ln_kernel<<<NTOK, 256>>>(x, norm_w);

    // 2. fused qkv+ff GEMM (q,k,v fp32 -> g_proj; gelu(ff) bf16 -> g_cat)
    hgemm<<<dim3(C7 / 128, NTOK / 128), 256>>>(
        (const __nv_bfloat16*)p_xnb, C, (const __nv_bfloat16*)p_wq, C,
        C, bqkv, nullptr, nullptr, nullptr, nullptr, 0);

    // 3. axial attention (mma.sync; q/k LN fused)
    attn_kernel<0><<<Bsz * 64 * HEADS, 128>>>(qnw, knw);
    attn_kernel<1><<<Bsz * 64 * HEADS, 128>>>(qnw, knw);

    // 4. fused output GEMM + residual epilogue
    hgemm<<<dim3(C / 128, NTOK / 128), 256>>>(
        (const __nv_bfloat16*)p_cat, CAT, (const __nv_bfloat16*)p_wc, CAT,
        CAT, bout, bmlp, x, gamma, out, 1);
}